// round 16
// baseline (speedup 1.0000x reference)
#include <cuda_runtime.h>
#include <cuda_fp16.h>
#include <cuda_bf16.h>
#include <cstdint>

#define BATCH 512
#define LSEQ 41
#define DMODEL 64
#define DINNER 128
#define NSTATE 16
#define DTRANK 4
#define KCONV 4
#define NSTACK 3
#define NLAYER 3
#define TP 46
#define TPAD 44
#define NPAIR 22
#define XNS 68

typedef unsigned long long ULL;
typedef unsigned int U32;

__device__ float g_stack[(size_t)NSTACK * BATCH * LSEQ * DMODEL];
__device__ float g_h1p[(size_t)4 * BATCH * 384];
__device__ float g_ipw32[(size_t)NSTACK*NLAYER*16384];
__device__ float g_opw32[(size_t)NSTACK*NLAYER*8192];
__device__ float g_xpw32[(size_t)NSTACK*NLAYER*4608];

__device__ __forceinline__ void ffma2(ULL& d, ULL a, ULL b) {
    asm("fma.rn.f32x2 %0, %1, %2, %0;" : "+l"(d) : "l"(a), "l"(b));
}
__device__ __forceinline__ ULL pack2(float x) {
    ULL r; asm("mov.b64 %0, {%1, %1};" : "=l"(r) : "f"(x)); return r;
}
__device__ __forceinline__ ULL pack2f(float lo, float hi) {
    ULL r; asm("mov.b64 %0, {%1, %2};" : "=l"(r) : "f"(lo), "f"(hi)); return r;
}
__device__ __forceinline__ ULL mul2(ULL a, ULL b) {
    ULL r; asm("mul.rn.f32x2 %0, %1, %2;" : "=l"(r) : "l"(a), "l"(b)); return r;
}
__device__ __forceinline__ void unpack2(ULL v, float& x, float& y) {
    asm("mov.b64 {%0, %1}, %2;" : "=f"(x), "=f"(y) : "l"(v));
}
__device__ __forceinline__ float siluf(float x) {
    return x * __fdividef(1.f, 1.f + __expf(-x));
}
__device__ __forceinline__ U32 tf32u(float x) {
    U32 r; asm("cvt.rna.tf32.f32 %0, %1;" : "=r"(r) : "f"(x)); return r;
}
__device__ __forceinline__ void mma_tf32(float* d, U32 a0, U32 a1, U32 a2, U32 a3,
                                         U32 b0, U32 b1) {
    asm("mma.sync.aligned.m16n8k8.row.col.f32.tf32.tf32.f32 "
        "{%0,%1,%2,%3}, {%4,%5,%6,%7}, {%8,%9}, {%0,%1,%2,%3};"
        : "+f"(d[0]), "+f"(d[1]), "+f"(d[2]), "+f"(d[3])
        : "r"(a0), "r"(a1), "r"(a2), "r"(a3), "r"(b0), "r"(b1));
}
__device__ __forceinline__ void cp16(U32 dst, const void* src) {
    asm volatile("cp.async.ca.shared.global [%0], [%1], 16;" :: "r"(dst), "l"(src) : "memory");
}
__device__ __forceinline__ void cp_commit() {
    asm volatile("cp.async.commit_group;" ::: "memory");
}
__device__ __forceinline__ void cp_wait0() { asm volatile("cp.async.wait_group 0;" ::: "memory"); }
__device__ __forceinline__ void cp_wait1() { asm volatile("cp.async.wait_group 1;" ::: "memory"); }

// ---- tf32-round weights once per launch ----
__global__ void __launch_bounds__(256)
cvt_weights(const float* __restrict__ in_proj, const float* __restrict__ out_proj,
            const float* __restrict__ x_proj)
{
    int i = blockIdx.x*256 + threadIdx.x;
    if (i < NSTACK*NLAYER*16384) g_ipw32[i] = __uint_as_float(tf32u(in_proj[i]));
    if (i < NSTACK*NLAYER*8192)  g_opw32[i] = __uint_as_float(tf32u(out_proj[i]));
    if (i < NSTACK*NLAYER*4608)  g_xpw32[i] = __uint_as_float(tf32u(x_proj[i]));
}

extern "C" __global__ void __launch_bounds__(128, 3)
mamba_stack_kernel(const int* __restrict__ input_ids,
                   const float* __restrict__ embedding,
                   const float* __restrict__ conv_w,
                   const float* __restrict__ conv_b,
                   const float* __restrict__ dt_w,
                   const float* __restrict__ dt_b,
                   const float* __restrict__ A_log,
                   const float* __restrict__ Dp,
                   const float* __restrict__ norm_w,
                   const float* __restrict__ norm_f_w)
{
    extern __shared__ float sm[];
    float* s_x    = sm;                      // 2624  [41][64] residual
    float* s_xn   = s_x    + LSEQ*DMODEL;    // 3264  [48][68] tf32 A (aliased by resh fp16)
    float* s_uT   = s_xn   + 48*XNS;         // 5888  [128][46]
    float* s_dbl  = s_uT   + DINNER*TP;      // 1476  [41][36]
    float* s_w    = s_dbl  + LSEQ*36;        // 5120  weight staging
    // total 18372 floats = 73488 B -> 3 CTAs/SM
    __half* s_resh = (__half*)s_xn;          // [128][46] fp16 silu(res)

    const int tid = threadIdx.x;
    const int b = blockIdx.x, s = blockIdx.y;
    const int warp = tid >> 5, lane = tid & 31;
    const int g  = lane >> 2, tg = lane & 3;
    const U32 swb = (U32)__cvta_generic_to_shared(s_w);

    // ---- embedding gather ----
    for (int i = tid; i < LSEQ*DMODEL; i += 128) {
        int t = i >> 6, d = i & 63;
        s_x[i] = embedding[input_ids[b*LSEQ + t]*DMODEL + d];
    }

    for (int l = 0; l < NLAYER; ++l) {
        const int wb = s*NLAYER + l;
        const float* ipw = g_ipw32 + (size_t)wb * 16384;
        const float* xpw = g_xpw32 + (size_t)wb * 4608;
        const float* opw = g_opw32 + (size_t)wb * 8192;
        __syncthreads();

        // prefetch in_proj chunk0 (8 k-rows x 256, staged stride 264)
        #pragma unroll
        for (int k = 0; k < 4; ++k) {
            int i = k*128 + tid;
            int row = i >> 6, c16 = i & 63;
            cp16(swb + (U32)(row*264 + c16*4)*4u, ipw + row*256 + c16*4);
        }
        cp_commit();

        // ---- rmsnorm -> xn [t][d] (tf32-rounded) ----
        {
            float nw0 = norm_w[wb*DMODEL + lane];
            float nw1 = norm_w[wb*DMODEL + 32 + lane];
            for (int t = warp; t < LSEQ; t += 4) {
                float v0 = s_x[t*DMODEL + lane];
                float v1 = s_x[t*DMODEL + 32 + lane];
                float ss = v0*v0 + v1*v1;
                #pragma unroll
                for (int o = 16; o; o >>= 1) ss += __shfl_xor_sync(0xffffffffu, ss, o);
                float inv = rsqrtf(ss * (1.f/64.f) + 1e-5f);
                *(U32*)&s_xn[t*XNS + lane]      = tf32u(v0 * inv * nw0);
                *(U32*)&s_xn[t*XNS + 32 + lane] = tf32u(v1 * inv * nw1);
            }
        }

        // ---- in_proj via tf32 mma: [48x64] @ [64x256]; warp w -> cols [64w,64w+64) ----
        {
            float acc[3][8][4];
            #pragma unroll
            for (int m = 0; m < 3; ++m)
                #pragma unroll
                for (int n = 0; n < 8; ++n)
                    #pragma unroll
                    for (int j = 0; j < 4; ++j) acc[m][n][j] = 0.f;
            for (int c = 0; c < 8; ++c) {
                __syncthreads();
                if (c < 7) {
                    int buf = (c+1) & 1;
                    #pragma unroll
                    for (int k = 0; k < 4; ++k) {
                        int i = k*128 + tid;
                        int row = i >> 6, c16 = i & 63;
                        cp16(swb + (U32)(buf*2112 + row*264 + c16*4)*4u,
                             ipw + (c+1)*2048 + row*256 + c16*4);
                    }
                    cp_commit();
                    cp_wait1();
                } else cp_wait0();
                __syncthreads();
                const float* ch_ = s_w + (c & 1)*2112;
                U32 b0[8], b1[8];
                #pragma unroll
                for (int nt = 0; nt < 8; ++nt) {
                    int col = warp*64 + nt*8 + g;
                    b0[nt] = *(const U32*)&ch_[tg*264 + col];
                    b1[nt] = *(const U32*)&ch_[(tg+4)*264 + col];
                }
                #pragma unroll
                for (int m = 0; m < 3; ++m) {
                    const float* ab = &s_xn[(m*16 + g)*XNS + c*8 + tg];
                    U32 a0 = *(const U32*)&ab[0];
                    U32 a1 = *(const U32*)&ab[8*XNS];
                    U32 a2 = *(const U32*)&ab[4];
                    U32 a3 = *(const U32*)&ab[8*XNS + 4];
                    #pragma unroll
                    for (int nt = 0; nt < 8; ++nt)
                        mma_tf32(acc[m][nt], a0, a1, a2, a3, b0[nt], b1[nt]);
                }
            }
            __syncthreads();   // all mmas done; xn dead -> resh may be written
            #pragma unroll
            for (int m = 0; m < 3; ++m)
                #pragma unroll
                for (int nt = 0; nt < 8; ++nt)
                    #pragma unroll
                    for (int j = 0; j < 4; ++j) {
                        int t = m*16 + g + ((j >> 1) & 1)*8;
                        int col = nt*8 + 2*tg + (j & 1);
                        if (t < LSEQ) {
                            if (warp < 2) {
                                s_uT[(warp*64 + col)*TP + t] = acc[m][nt][j];
                            } else {
                                s_resh[((warp-2)*64 + col)*TP + t] =
                                    __float2half(siluf(acc[m][nt][j]));
                            }
                        }
                    }
        }
        __syncthreads();   // u + resh visible; s_w free

        // prefetch x_proj weights (stride 40; 36 floats/row = 9 cp16/row)
        #pragma unroll
        for (int k = 0; k < 9; ++k) {
            int j = k*128 + tid;
            int row = j / 9, seg = j - row*9;
            cp16(swb + (U32)(row*40 + seg*4)*4u, xpw + row*36 + seg*4);
        }
        cp_commit();

        // ---- causal conv(K=4)+bias+silu, thread = channel tid; u stored tf32 ----
        {
            float ul[TPAD];
            const ULL* ur = (const ULL*)&s_uT[tid*TP];
            #pragma unroll
            for (int k = 0; k < NPAIR; ++k) unpack2(ur[k], ul[2*k], ul[2*k+1]);
            const float* cw = conv_w + (size_t)(wb*DINNER + tid)*KCONV;
            float c0 = cw[0], c1 = cw[1], c2 = cw[2], c3 = cw[3];
            float cb = conv_b[wb*DINNER + tid];
            #pragma unroll
            for (int t = 0; t < LSEQ; ++t) {
                float a = ul[t]*c3 + cb;
                if (t >= 1) a += ul[t-1]*c2;
                if (t >= 2) a += ul[t-2]*c1;
                if (t >= 3) a += ul[t-3]*c0;
                *(U32*)&s_uT[tid*TP + t] = tf32u(siluf(a));
            }
            #pragma unroll
            for (int t = LSEQ; t < TPAD; ++t) s_uT[tid*TP + t] = 0.f;
        }
        cp_wait0();
        __syncthreads();

        // ---- x_proj via tf32 mma: dbl[48x40] = u^T[48x128] @ xp[128x40] ----
        {
            float xacc[4][4];
            #pragma unroll
            for (int f = 0; f < 4; ++f)
                #pragma unroll
                for (int j = 0; j < 4; ++j) xacc[f][j] = 0.f;
            if (warp < 3) {
                const int m = warp;
                #pragma unroll
                for (int k8 = 0; k8 < 16; ++k8) {
                    const float* ab = &s_uT[(k8*8 + tg)*TP + m*16 + g];
                    U32 a0 = *(const U32*)&ab[0];
                    U32 a1 = *(const U32*)&ab[8];
                    U32 a2 = *(const U32*)&ab[4*TP];
                    U32 a3 = *(const U32*)&ab[4*TP + 8];
                    #pragma unroll
                    for (int nt = 0; nt < 4; ++nt) {
                        U32 b0 = *(const U32*)&s_w[(k8*8 + tg)*40 + nt*8 + g];
                        U32 b1 = *(const U32*)&s_w[(k8*8 + tg + 4)*40 + nt*8 + g];
                        mma_tf32(xacc[nt], a0, a1, a2, a3, b0, b1);
                    }
                }
            } else {
                #pragma unroll
                for (int k8 = 0; k8 < 16; ++k8) {
                    U32 b0 = *(const U32*)&s_w[(k8*8 + tg)*40 + 32 + g];
                    U32 b1 = *(const U32*)&s_w[(k8*8 + tg + 4)*40 + 32 + g];
                    #pragma unroll
                    for (int m = 0; m < 3; ++m) {
                        const float* ab = &s_uT[(k8*8 + tg)*TP + m*16 + g];
                        U32 a0 = *(const U32*)&ab[0];
                        U32 a1 = *(const U32*)&ab[8];
                        U32 a2 = *(const U32*)&ab[4*TP];
                        U32 a3 = *(const U32*)&ab[4*TP + 8];
                        mma_tf32(xacc[m], a0, a1, a2, a3, b0, b1);
                    }
                }
            }
            if (warp < 3) {
                const int m = warp;
                #pragma unroll
                for (int nt = 0; nt < 4; ++nt)
                    #pragma unroll
                    for (int j = 0; j < 4; ++j) {
                        int t = m*16 + g + ((j >> 1) & 1)*8;
                        int col = nt*8 + 2*tg + (j & 1);
                        if (t < LSEQ) s_dbl[t*36 + col] = xacc[nt][j];
                    }
            } else {
                #pragma unroll
                for (int m = 0; m < 3; ++m)
                    #pragma unroll
                    for (int j = 0; j < 4; ++j) {
                        int t = m*16 + g + ((j >> 1) & 1)*8;
                        int col = 32 + 2*tg + (j & 1);
                        if (t < LSEQ && col < 36) s_dbl[t*36 + col] = xacc[m][j];
                    }
            }
        }
        __syncthreads();   // dbl visible; s_w free

        // prefetch out_proj chunk0 (32 k-rows x 64, staged stride 72)
        #pragma unroll
        for (int k = 0; k < 2; ++k) {
            int i = k*128 + tid;
            int row = i >> 4, c16 = i & 15;
            cp16(swb + (U32)(row*72 + c16*4)*4u, opw + row*64 + c16*4);
        }
        cp_commit();

        // ---- selective scan (gate fused into store; B/C via LDS.128) ----
        {
            float dw0 = dt_w[(wb*DTRANK+0)*DINNER + tid];
            float dw1 = dt_w[(wb*DTRANK+1)*DINNER + tid];
            float dw2 = dt_w[(wb*DTRANK+2)*DINNER + tid];
            float dw3 = dt_w[(wb*DTRANK+3)*DINNER + tid];
            float dtbv = dt_b[wb*DINNER + tid];
            float dpv  = Dp[wb*DINNER + tid];
            const float* al = A_log + (size_t)(wb*DINNER + tid)*NSTATE;
            bool fast = true;
            #pragma unroll
            for (int n = 0; n < NSTATE; ++n) {
                float a = -__expf(al[n]);
                float tgt = (float)(n + 1);
                fast = fast && (fabsf(a + tgt) < 1e-3f * tgt);
            }
            ULL h2[8];
            #pragma unroll
            for (int k = 0; k < 8; ++k) h2[k] = 0ull;
            for (int t = 0; t < LSEQ; ++t) {
                const float* dr = &s_dbl[t*36];
                const float4 qd = *(const float4*)dr;
                float xr = fmaf(qd.x,dw0, fmaf(qd.y,dw1, fmaf(qd.z,dw2, fmaf(qd.w,dw3, dtbv))));
                float e = __expf(xr);
                float dtv, q;
                if (xr > 15.f) { dtv = xr; q = __expf(-xr); }
                else { float d1 = 1.f + e; dtv = __logf(d1); q = __fdividef(1.f, d1); }
                float ut = s_uT[tid*TP + t];
                ULL dtu2 = pack2(dtv * ut);
                ULL dA2[8];
                if (fast) {
                    float q2 = q*q, q4 = q2*q2, q8 = q4*q4;
                    ULL q2p = pack2(q2), q4p = pack2(q4), q8p = pack2(q8);
                    dA2[0] = pack2f(q, q2);
                    dA2[1] = mul2(dA2[0], q2p);
                    dA2[2] = mul2(dA2[0], q4p);
                    dA2[3] = mul2(dA2[1], q4p);
                    dA2[4] = mul2(dA2[0], q8p);
                    dA2[5] = mul2(dA2[1], q8p);
                    dA2[6] = mul2(dA2[2], q8p);
                    dA2[7] = mul2(dA2[3], q8p);
                } else {
                    #pragma unroll
                    for (int k = 0; k < 8; ++k)
                        dA2[k] = pack2f(__expf(-dtv*__expf(al[2*k])),
                                        __expf(-dtv*__expf(al[2*k+1])));
                }
                // B at dr+4, C at dr+20: both 16B-aligned (t*144+16, t*144+80)
                const ulonglong2* bq = (const ulonglong2*)(dr + 4);
                ulonglong2 bA = bq[0], bB = bq[1], bC = bq[2], bD = bq[3];
                const ulonglong2* cq = (const ulonglong2*)(dr + 20);
                ulonglong2 cA = cq[0], cB = cq[1], cC = cq[2], cD = cq[3];
                ULL Bp[8] = {bA.x, bA.y, bB.x, bB.y, bC.x, bC.y, bD.x, bD.y};
                ULL Cp[8] = {cA.x, cA.y, cB.x, cB.y, cC.x, cC.y, cD.x, cD.y};
                ULL ya = 0ull, yb = 0ull;
                #pragma unroll
                for (int k = 0; k < 8; ++k) {
                    ULL tmp = mul2(dtu2, Bp[k]);
                    ffma2(tmp, dA2[k], h2[k]);
                    h2[k] = tmp;
                    if (k < 4) ffma2(ya, h2[k], Cp[k]);
                    else       ffma2(yb, h2[k], Cp[k]);
                }
                float a0v, a1v, b0v, b1v;
                unpack2(ya, a0v, a1v);
                unpack2(yb, b0v, b1v);
                float z = ((a0v + b0v) + (a1v + b1v)) + ut*dpv;
                float res = __half2float(s_resh[tid*TP + t]);
                *(U32*)&s_uT[tid*TP + t] = tf32u(z * res);   // gated, tf32 A of out_proj
            }
        }

        // ---- out_proj via tf32 mma: [48x128] @ [128x64], += residual ----
        {
            float acc[6][4];
            #pragma unroll
            for (int f = 0; f < 6; ++f)
                #pragma unroll
                for (int j = 0; j < 4; ++j) acc[f][j] = 0.f;
            for (int c = 0; c < 4; ++c) {
                __syncthreads();             // scan/gate done (c=0) / prev chunk compute done
                if (c < 3) {
                    int buf = (c+1) & 1;
                    #pragma unroll
                    for (int k = 0; k < 2; ++k) {
                        int i = k*128 + tid;
                        int row = i >> 4, c16 = i & 15;
                        cp16(swb + (U32)(buf*1152 + row*72 + c16*4)*4u,
                             opw + (c+1)*1024 + row*64 + c16*4);
                    }
                    cp_commit();
                    cp_wait1();
                } else cp_wait0();
                __syncthreads();
                const float* ch_ = s_w + (c & 1)*1152;
                #pragma unroll
                for (int k8 = 0; k8 < 4; ++k8) {
                    U32 b0[2], b1[2];
                    #pragma unroll
                    for (int nt = 0; nt < 2; ++nt) {
                        int col = (2*warp + nt)*8 + g;
                        b0[nt] = *(const U32*)&ch_[(k8*8 + tg)*72 + col];
                        b1[nt] = *(const U32*)&ch_[(k8*8 + tg + 4)*72 + col];
                    }
                    const int kg = c*32 + k8*8;
                    #pragma unroll
                    for (int m = 0; m < 3; ++m) {
                        U32 a0 = *(const U32*)&s_uT[(kg+tg)*TP   + m*16 + g];
                        U32 a1 = *(const U32*)&s_uT[(kg+tg)*TP   + m*16 + g + 8];
                        U32 a2 = *(const U32*)&s_uT[(kg+tg+4)*TP + m*16 + g];
                        U32 a3 = *(const U32*)&s_uT[(kg+tg+4)*TP + m*16 + g + 8];
                        #pragma unroll
                        for (int nt = 0; nt < 2; ++nt)
                            mma_tf32(acc[m*2 + nt], a0, a1, a2, a3, b0[nt], b1[nt]);
                    }
                }
            }
            __syncthreads();
            #pragma unroll
            for (int m = 0; m < 3; ++m)
                #pragma unroll
                for (int nt = 0; nt < 2; ++nt)
                    #pragma unroll
                    for (int j = 0; j < 4; ++j) {
                        int t = m*16 + g + ((j >> 1) & 1)*8;
                        int col = (2*warp + nt)*8 + 2*tg + (j & 1);
                        if (t < LSEQ) s_x[t*DMODEL + col] += acc[m*2 + nt][j];
                    }
        }
    }

    // ---- final rmsnorm + store stack output ----
    __syncthreads();
    {
        float nw0 = norm_f_w[lane], nw1 = norm_f_w[32 + lane];
        for (int t = warp; t < LSEQ; t += 4) {
            float v0 = s_x[t*DMODEL + lane];
            float v1 = s_x[t*DMODEL + 32 + lane];
            float ss = v0*v0 + v1*v1;
            #pragma unroll
            for (int o = 16; o; o >>= 1) ss += __shfl_xor_sync(0xffffffffu, ss, o);
            float inv = rsqrtf(ss * (1.f/64.f) + 1e-5f);
            float* dst = g_stack + ((size_t)(s*BATCH + b)*LSEQ + t)*DMODEL;
            dst[lane]      = v0 * inv * nw0;
            dst[lane + 32] = v1 * inv * nw1;
        }
    }
}

// ---- head GEMM (FFMA2): partial[kz] = fused[512x2624] @ W1 chunk; 64x64 tiles, split-K=4 ----
__global__ void __launch_bounds__(256)
head_gemm1(const float* __restrict__ fusion_w, const float* __restrict__ W1)
{
    __shared__ float As[64][33];
    __shared__ float Ws[32][64];
    const int tid = threadIdx.x;
    const int rb = blockIdx.x, cb = blockIdx.y, kz = blockIdx.z;
    float f0 = fusion_w[0], f1 = fusion_w[1], f2 = fusion_w[2];
    float m = fmaxf(f0, fmaxf(f1, f2));
    float e0 = expf(f0-m), e1 = expf(f1-m), e2 = expf(f2-m);
    float inv = 1.f/(e0+e1+e2);
    e0 *= inv; e1 *= inv; e2 *= inv;
    const int tx = tid & 15, ty = tid >> 4;
    ULL acc2[4][2];
    #pragma unroll
    for (int r = 0; r < 4; ++r) { acc2[r][0] = 0ull; acc2[r][1] = 0ull; }
    const int KT = LSEQ*DMODEL;
    const size_t SS = (size_t)BATCH * KT;
    const int kt0    = (kz < 2) ? 21*kz : 42 + 20*(kz - 2);
    const int ntiles = (kz < 2) ? 21 : 20;
    for (int it = 0; it < ntiles; ++it) {
        const int kc = kt0 + it;
        __syncthreads();
        #pragma unroll
        for (int i = tid; i < 2048; i += 256) {
            int r = i >> 5, kk = i & 31;
            size_t base = (size_t)(rb*64 + r)*KT + kc*32 + kk;
            As[r][kk] = e0*g_stack[base] + e1*g_stack[base + SS] + e2*g_stack[base + 2*SS];
        }
        #pragma unroll
        for (int i = tid; i < 2048; i += 256) {
            int kk = i >> 6, j = i & 63;
            Ws[kk][j] = W1[(size_t)(kc*32 + kk)*384 + cb*64 + j];
        }
        __syncthreads();
        #pragma unroll
        for (int kk = 0; kk < 32; ++kk) {
            const ULL* wp = (const ULL*)&Ws[kk][tx*4];
            ULL w0 = wp[0], w1 = wp[1];
            ULL a0 = pack2(As[ty*4+0][kk]);
            ULL a1 = pack2(As[ty*4+1][kk]);
            ULL a2 = pack2(As[ty*4+2][kk]);
            ULL a3 = pack2(As[ty*4+3][kk]);
            ffma2(acc2[0][0], a0, w0); ffma2(acc2[0][1], a0, w1);
            ffma2(acc2[1][0], a1, w0); ffma2(acc2[1][1], a1, w1);
            ffma2(acc2[2][0], a2, w0); ffma2(acc2[2][1], a2, w1);
            ffma2(acc2[3][0], a3, w0); ffma2(acc2[3][1], a3, w1);
        }
    }
    float* dst = g_h1p + (size_t)kz * BATCH * 384;
    #pragma unroll
    for (int r = 0; r < 4; ++r) {
        int row = rb*64 + ty*4 + r;
        #pragma unroll
        for (int p = 0; p < 2; ++p) {
            float v0, v1; unpack2(acc2[r][p], v0, v1);
            int colg = cb*64 + tx*4 + p*2;
            dst[(size_t)row*384 + colg]     = v0;
            dst[(size_t)row*384 + colg + 1] = v1;
        }
    }
}

// ---- tail: one block per batch row ----
__global__ void __launch_bounds__(128)
head_final(const float* __restrict__ b1,
           const float* __restrict__ W2, const float* __restrict__ b2,
           const float* __restrict__ W3, const float* __restrict__ b3,
           float* __restrict__ out)
{
    __shared__ float hv[384];
    __shared__ float part[8][16];
    const int tid = threadIdx.x;
    const int b = blockIdx.x;
    const float* p0 = g_h1p + (size_t)b*384;
    const float* p1 = p0 + (size_t)BATCH*384;
    const float* p2 = p1 + (size_t)BATCH*384;
    const float* p3 = p2 + (size_t)BATCH*384;
    #pragma unroll
    for (int i = tid; i < 384; i += 128)
        hv[i] = fmaxf(p0[i] + p1[i] + p2[i] + p3[i] + b1[i], 0.f);
    __syncthreads();
    const int j = tid & 15, seg = tid >> 4;
    float acc = 0.f;
    #pragma unroll 8
    for (int i = seg*48; i < seg*48 + 48; ++i)
        acc += hv[i] * W2[i*16 + j];
    part[seg][j] = acc;
    __syncthreads();
    if (tid < 16) {
        float sum = part[0][tid] + part[1][tid] + part[2][tid] + part[3][tid]
                  + part[4][tid] + part[5][tid] + part[6][tid] + part[7][tid];
        float h2v = fmaxf(sum + b2[tid], 0.f);
        float pr = h2v * W3[tid];
        #pragma unroll
        for (int o = 8; o; o >>= 1) pr += __shfl_xor_sync(0xffffu, pr, o);
        if (tid == 0) out[b] = __fdividef(1.f, 1.f + __expf(-(pr + b3[0])));
    }
}

extern "C" void kernel_launch(void* const* d_in, const int* in_sizes, int n_in,
                              void* d_out, int out_size) {
    const int*   input_ids = (const int*)d_in[0];
    const float* embedding = (const float*)d_in[1];
    const float* in_proj   = (const float*)d_in[2];
    const float* conv_w    = (const float*)d_in[3];
    const float* conv_b    = (const float*)d_in[4];
    const float* x_proj    = (const float*)d_in[5];
    const float* dt_w      = (const float*)d_in[6];
    const float* dt_b      = (const float*)d_in[7];
    const float* A_log     = (const float*)d_in[8];
    const float* Dp        = (const float*)d_in[9];
    const float* out_proj  = (const float*)d_in[10];
    const float* norm_w    = (const float*)d_in[11];
    const float* norm_f_w  = (const float*)d_in[12];
    const float* fusion_w  = (const float*)d_in[13];
    const float* W1        = (const float*)d_in[14];
    const float* b1        = (const float*)d_in[15];
    const float* W2        = (const float*)d_in[16];
    const float* b2        = (const float*)d_in[17];
    const float* W3        = (const float*)d_in[18];
    const float* b3        = (const float*)d_in[19];
    float* out = (float*)d_out;
    (void)in_sizes; (void)n_in; (void)out_size;

    cvt_weights<<<(NSTACK*NLAYER*16384 + 255)/256, 256>>>(in_proj, out_proj, x_proj);

    const int smemA = 18372 * 4;  // 73488 bytes -> 3 CTAs/SM
    cudaFuncSetAttribute(mamba_stack_kernel,
                         cudaFuncAttributeMaxDynamicSharedMemorySize, smemA);
    mamba_stack_kernel<<<dim3(BATCH, NSTACK), 128, smemA>>>(
        input_ids, embedding, conv_w, conv_b, dt_w, dt_b,
        A_log, Dp, norm_w, norm_f_w);
    head_gemm1<<<dim3(8, 6, 4), 256>>>(fusion_w, W1);
    head_final<<<BATCH, 128>>>(b1, W2, b2, W3, b3, out);
}

// round 17
// speedup vs baseline: 1.0429x; 1.0429x over previous
#include <cuda_runtime.h>
#include <cuda_fp16.h>
#include <cuda_bf16.h>
#include <cstdint>

#define BATCH 512
#define LSEQ 41
#define DMODEL 64
#define DINNER 128
#define NSTATE 16
#define DTRANK 4
#define KCONV 4
#define NSTACK 3
#define NLAYER 3
#define TP 46
#define TPAD 44
#define NPAIR 22
#define XNS 68
#define KSPLIT 8

typedef unsigned long long ULL;
typedef unsigned int U32;

__device__ float g_stack[(size_t)NSTACK * BATCH * LSEQ * DMODEL];
__device__ float g_fused[(size_t)BATCH * LSEQ * DMODEL];
__device__ float g_h1p[(size_t)KSPLIT * BATCH * 384];
__device__ float g_ipw32[(size_t)NSTACK*NLAYER*16384];
__device__ float g_opw32[(size_t)NSTACK*NLAYER*8192];
__device__ float g_xpw32[(size_t)NSTACK*NLAYER*4608];

__device__ __forceinline__ void ffma2(ULL& d, ULL a, ULL b) {
    asm("fma.rn.f32x2 %0, %1, %2, %0;" : "+l"(d) : "l"(a), "l"(b));
}
__device__ __forceinline__ ULL pack2(float x) {
    ULL r; asm("mov.b64 %0, {%1, %1};" : "=l"(r) : "f"(x)); return r;
}
__device__ __forceinline__ ULL pack2f(float lo, float hi) {
    ULL r; asm("mov.b64 %0, {%1, %2};" : "=l"(r) : "f"(lo), "f"(hi)); return r;
}
__device__ __forceinline__ ULL mul2(ULL a, ULL b) {
    ULL r; asm("mul.rn.f32x2 %0, %1, %2;" : "=l"(r) : "l"(a), "l"(b)); return r;
}
__device__ __forceinline__ void unpack2(ULL v, float& x, float& y) {
    asm("mov.b64 {%0, %1}, %2;" : "=f"(x), "=f"(y) : "l"(v));
}
__device__ __forceinline__ float siluf(float x) {
    return x * __fdividef(1.f, 1.f + __expf(-x));
}
__device__ __forceinline__ U32 tf32u(float x) {
    U32 r; asm("cvt.rna.tf32.f32 %0, %1;" : "=r"(r) : "f"(x)); return r;
}
__device__ __forceinline__ void mma_tf32(float* d, U32 a0, U32 a1, U32 a2, U32 a3,
                                         U32 b0, U32 b1) {
    asm("mma.sync.aligned.m16n8k8.row.col.f32.tf32.tf32.f32 "
        "{%0,%1,%2,%3}, {%4,%5,%6,%7}, {%8,%9}, {%0,%1,%2,%3};"
        : "+f"(d[0]), "+f"(d[1]), "+f"(d[2]), "+f"(d[3])
        : "r"(a0), "r"(a1), "r"(a2), "r"(a3), "r"(b0), "r"(b1));
}
__device__ __forceinline__ void cp16(U32 dst, const void* src) {
    asm volatile("cp.async.ca.shared.global [%0], [%1], 16;" :: "r"(dst), "l"(src) : "memory");
}
__device__ __forceinline__ void cp_commit() {
    asm volatile("cp.async.commit_group;" ::: "memory");
}
__device__ __forceinline__ void cp_wait0() { asm volatile("cp.async.wait_group 0;" ::: "memory"); }
__device__ __forceinline__ void cp_wait1() { asm volatile("cp.async.wait_group 1;" ::: "memory"); }

// ---- tf32-round weights once per launch ----
__global__ void __launch_bounds__(256)
cvt_weights(const float* __restrict__ in_proj, const float* __restrict__ out_proj,
            const float* __restrict__ x_proj)
{
    int i = blockIdx.x*256 + threadIdx.x;
    if (i < NSTACK*NLAYER*16384) g_ipw32[i] = __uint_as_float(tf32u(in_proj[i]));
    if (i < NSTACK*NLAYER*8192)  g_opw32[i] = __uint_as_float(tf32u(out_proj[i]));
    if (i < NSTACK*NLAYER*4608)  g_xpw32[i] = __uint_as_float(tf32u(x_proj[i]));
}

extern "C" __global__ void __launch_bounds__(128, 3)
mamba_stack_kernel(const int* __restrict__ input_ids,
                   const float* __restrict__ embedding,
                   const float* __restrict__ conv_w,
                   const float* __restrict__ conv_b,
                   const float* __restrict__ dt_w,
                   const float* __restrict__ dt_b,
                   const float* __restrict__ A_log,
                   const float* __restrict__ Dp,
                   const float* __restrict__ norm_w,
                   const float* __restrict__ norm_f_w)
{
    extern __shared__ float sm[];
    float* s_x    = sm;                      // 2624  [41][64] residual
    float* s_xn   = s_x    + LSEQ*DMODEL;    // 3264  [48][68] tf32 A (aliased by resh fp16)
    float* s_uT   = s_xn   + 48*XNS;         // 5888  [128][46]
    float* s_dbl  = s_uT   + DINNER*TP;      // 1476  [41][36]
    float* s_w    = s_dbl  + LSEQ*36;        // 5120  weight staging
    // total 18372 floats = 73488 B -> 3 CTAs/SM
    __half* s_resh = (__half*)s_xn;          // [128][46] fp16 silu(res)

    const int tid = threadIdx.x;
    const int b = blockIdx.x, s = blockIdx.y;
    const int warp = tid >> 5, lane = tid & 31;
    const int g  = lane >> 2, tg = lane & 3;
    const U32 swb = (U32)__cvta_generic_to_shared(s_w);

    // ---- embedding gather ----
    for (int i = tid; i < LSEQ*DMODEL; i += 128) {
        int t = i >> 6, d = i & 63;
        s_x[i] = embedding[input_ids[b*LSEQ + t]*DMODEL + d];
    }

    for (int l = 0; l < NLAYER; ++l) {
        const int wb = s*NLAYER + l;
        const float* ipw = g_ipw32 + (size_t)wb * 16384;
        const float* xpw = g_xpw32 + (size_t)wb * 4608;
        const float* opw = g_opw32 + (size_t)wb * 8192;
        __syncthreads();

        // prefetch in_proj chunk0 (8 k-rows x 256, staged stride 264)
        #pragma unroll
        for (int k = 0; k < 4; ++k) {
            int i = k*128 + tid;
            int row = i >> 6, c16 = i & 63;
            cp16(swb + (U32)(row*264 + c16*4)*4u, ipw + row*256 + c16*4);
        }
        cp_commit();

        // ---- rmsnorm -> xn [t][d] (tf32-rounded) ----
        {
            float nw0 = norm_w[wb*DMODEL + lane];
            float nw1 = norm_w[wb*DMODEL + 32 + lane];
            for (int t = warp; t < LSEQ; t += 4) {
                float v0 = s_x[t*DMODEL + lane];
                float v1 = s_x[t*DMODEL + 32 + lane];
                float ss = v0*v0 + v1*v1;
                #pragma unroll
                for (int o = 16; o; o >>= 1) ss += __shfl_xor_sync(0xffffffffu, ss, o);
                float inv = rsqrtf(ss * (1.f/64.f) + 1e-5f);
                *(U32*)&s_xn[t*XNS + lane]      = tf32u(v0 * inv * nw0);
                *(U32*)&s_xn[t*XNS + 32 + lane] = tf32u(v1 * inv * nw1);
            }
        }

        // ---- in_proj via tf32 mma: [48x64] @ [64x256]; warp w -> cols [64w,64w+64) ----
        {
            float acc[3][8][4];
            #pragma unroll
            for (int m = 0; m < 3; ++m)
                #pragma unroll
                for (int n = 0; n < 8; ++n)
                    #pragma unroll
                    for (int j = 0; j < 4; ++j) acc[m][n][j] = 0.f;
            for (int c = 0; c < 8; ++c) {
                __syncthreads();
                if (c < 7) {
                    int buf = (c+1) & 1;
                    #pragma unroll
                    for (int k = 0; k < 4; ++k) {
                        int i = k*128 + tid;
                        int row = i >> 6, c16 = i & 63;
                        cp16(swb + (U32)(buf*2112 + row*264 + c16*4)*4u,
                             ipw + (c+1)*2048 + row*256 + c16*4);
                    }
                    cp_commit();
                    cp_wait1();
                } else cp_wait0();
                __syncthreads();
                const float* ch_ = s_w + (c & 1)*2112;
                U32 b0[8], b1[8];
                #pragma unroll
                for (int nt = 0; nt < 8; ++nt) {
                    int col = warp*64 + nt*8 + g;
                    b0[nt] = *(const U32*)&ch_[tg*264 + col];
                    b1[nt] = *(const U32*)&ch_[(tg+4)*264 + col];
                }
                #pragma unroll
                for (int m = 0; m < 3; ++m) {
                    const float* ab = &s_xn[(m*16 + g)*XNS + c*8 + tg];
                    U32 a0 = *(const U32*)&ab[0];
                    U32 a1 = *(const U32*)&ab[8*XNS];
                    U32 a2 = *(const U32*)&ab[4];
                    U32 a3 = *(const U32*)&ab[8*XNS + 4];
                    #pragma unroll
                    for (int nt = 0; nt < 8; ++nt)
                        mma_tf32(acc[m][nt], a0, a1, a2, a3, b0[nt], b1[nt]);
                }
            }
            __syncthreads();   // all mmas done; xn dead -> resh may be written
            #pragma unroll
            for (int m = 0; m < 3; ++m)
                #pragma unroll
                for (int nt = 0; nt < 8; ++nt)
                    #pragma unroll
                    for (int j = 0; j < 4; ++j) {
                        int t = m*16 + g + ((j >> 1) & 1)*8;
                        int col = nt*8 + 2*tg + (j & 1);
                        if (t < LSEQ) {
                            if (warp < 2) {
                                s_uT[(warp*64 + col)*TP + t] = acc[m][nt][j];
                            } else {
                                s_resh[((warp-2)*64 + col)*TP + t] =
                                    __float2half(siluf(acc[m][nt][j]));
                            }
                        }
                    }
        }
        __syncthreads();   // u + resh visible; s_w free

        // prefetch x_proj weights (stride 40; 36 floats/row = 9 cp16/row)
        #pragma unroll
        for (int k = 0; k < 9; ++k) {
            int j = k*128 + tid;
            int row = j / 9, seg = j - row*9;
            cp16(swb + (U32)(row*40 + seg*4)*4u, xpw + row*36 + seg*4);
        }
        cp_commit();

        // ---- causal conv(K=4)+bias+silu, thread = channel tid; u stored tf32 ----
        {
            float ul[TPAD];
            const ULL* ur = (const ULL*)&s_uT[tid*TP];
            #pragma unroll
            for (int k = 0; k < NPAIR; ++k) unpack2(ur[k], ul[2*k], ul[2*k+1]);
            const float* cw = conv_w + (size_t)(wb*DINNER + tid)*KCONV;
            float c0 = cw[0], c1 = cw[1], c2 = cw[2], c3 = cw[3];
            float cb = conv_b[wb*DINNER + tid];
            #pragma unroll
            for (int t = 0; t < LSEQ; ++t) {
                float a = ul[t]*c3 + cb;
                if (t >= 1) a += ul[t-1]*c2;
                if (t >= 2) a += ul[t-2]*c1;
                if (t >= 3) a += ul[t-3]*c0;
                *(U32*)&s_uT[tid*TP + t] = tf32u(siluf(a));
            }
            #pragma unroll
            for (int t = LSEQ; t < TPAD; ++t) s_uT[tid*TP + t] = 0.f;
        }
        cp_wait0();
        __syncthreads();

        // ---- x_proj via tf32 mma: dbl[48x40] = u^T[48x128] @ xp[128x40] ----
        {
            float xacc[4][4];
            #pragma unroll
            for (int f = 0; f < 4; ++f)
                #pragma unroll
                for (int j = 0; j < 4; ++j) xacc[f][j] = 0.f;
            if (warp < 3) {
                const int m = warp;
                #pragma unroll
                for (int k8 = 0; k8 < 16; ++k8) {
                    const float* ab = &s_uT[(k8*8 + tg)*TP + m*16 + g];
                    U32 a0 = *(const U32*)&ab[0];
                    U32 a1 = *(const U32*)&ab[8];
                    U32 a2 = *(const U32*)&ab[4*TP];
                    U32 a3 = *(const U32*)&ab[4*TP + 8];
                    #pragma unroll
                    for (int nt = 0; nt < 4; ++nt) {
                        U32 b0 = *(const U32*)&s_w[(k8*8 + tg)*40 + nt*8 + g];
                        U32 b1 = *(const U32*)&s_w[(k8*8 + tg + 4)*40 + nt*8 + g];
                        mma_tf32(xacc[nt], a0, a1, a2, a3, b0, b1);
                    }
                }
            } else {
                #pragma unroll
                for (int k8 = 0; k8 < 16; ++k8) {
                    U32 b0 = *(const U32*)&s_w[(k8*8 + tg)*40 + 32 + g];
                    U32 b1 = *(const U32*)&s_w[(k8*8 + tg + 4)*40 + 32 + g];
                    #pragma unroll
                    for (int m = 0; m < 3; ++m) {
                        const float* ab = &s_uT[(k8*8 + tg)*TP + m*16 + g];
                        U32 a0 = *(const U32*)&ab[0];
                        U32 a1 = *(const U32*)&ab[8];
                        U32 a2 = *(const U32*)&ab[4*TP];
                        U32 a3 = *(const U32*)&ab[4*TP + 8];
                        mma_tf32(xacc[m], a0, a1, a2, a3, b0, b1);
                    }
                }
            }
            if (warp < 3) {
                const int m = warp;
                #pragma unroll
                for (int nt = 0; nt < 4; ++nt)
                    #pragma unroll
                    for (int j = 0; j < 4; ++j) {
                        int t = m*16 + g + ((j >> 1) & 1)*8;
                        int col = nt*8 + 2*tg + (j & 1);
                        if (t < LSEQ) s_dbl[t*36 + col] = xacc[nt][j];
                    }
            } else {
                #pragma unroll
                for (int m = 0; m < 3; ++m)
                    #pragma unroll
                    for (int j = 0; j < 4; ++j) {
                        int t = m*16 + g + ((j >> 1) & 1)*8;
                        int col = 32 + 2*tg + (j & 1);
                        if (t < LSEQ && col < 36) s_dbl[t*36 + col] = xacc[m][j];
                    }
            }
        }
        __syncthreads();   // dbl visible; s_w free

        // prefetch out_proj chunk0 (32 k-rows x 64, staged stride 72)
        #pragma unroll
        for (int k = 0; k < 2; ++k) {
            int i = k*128 + tid;
            int row = i >> 4, c16 = i & 15;
            cp16(swb + (U32)(row*72 + c16*4)*4u, opw + row*64 + c16*4);
        }
        cp_commit();

        // ---- selective scan ----
        {
            float dw0 = dt_w[(wb*DTRANK+0)*DINNER + tid];
            float dw1 = dt_w[(wb*DTRANK+1)*DINNER + tid];
            float dw2 = dt_w[(wb*DTRANK+2)*DINNER + tid];
            float dw3 = dt_w[(wb*DTRANK+3)*DINNER + tid];
            float dtbv = dt_b[wb*DINNER + tid];
            float dpv  = Dp[wb*DINNER + tid];
            float Av[NSTATE];
            const float* al = A_log + (size_t)(wb*DINNER + tid)*NSTATE;
            bool fast = true;
            #pragma unroll
            for (int n = 0; n < NSTATE; ++n) {
                Av[n] = -__expf(al[n]);
                float tgt = (float)(n + 1);
                fast = fast && (fabsf(Av[n] + tgt) < 1e-3f * tgt);
            }
            ULL h2[8];
            #pragma unroll
            for (int k = 0; k < 8; ++k) h2[k] = 0ull;
            for (int t = 0; t < LSEQ; ++t) {
                const float* dr = &s_dbl[t*36];
                const float4 qd = *(const float4*)dr;
                float xr = fmaf(qd.x,dw0, fmaf(qd.y,dw1, fmaf(qd.z,dw2, fmaf(qd.w,dw3, dtbv))));
                float e = __expf(xr);
                float dtv, q;
                if (xr > 15.f) { dtv = xr; q = __expf(-xr); }
                else { float d1 = 1.f + e; dtv = __logf(d1); q = __fdividef(1.f, d1); }
                float ut = s_uT[tid*TP + t];
                ULL dtu2 = pack2(dtv * ut);
                ULL dA2[8];
                if (fast) {
                    float q2 = q*q, q4 = q2*q2, q8 = q4*q4;
                    ULL q2p = pack2(q2), q4p = pack2(q4), q8p = pack2(q8);
                    dA2[0] = pack2f(q, q2);
                    dA2[1] = mul2(dA2[0], q2p);
                    dA2[2] = mul2(dA2[0], q4p);
                    dA2[3] = mul2(dA2[1], q4p);
                    dA2[4] = mul2(dA2[0], q8p);
                    dA2[5] = mul2(dA2[1], q8p);
                    dA2[6] = mul2(dA2[2], q8p);
                    dA2[7] = mul2(dA2[3], q8p);
                } else {
                    #pragma unroll
                    for (int k = 0; k < 8; ++k)
                        dA2[k] = pack2f(__expf(dtv*Av[2*k]), __expf(dtv*Av[2*k+1]));
                }
                const ULL* bp = (const ULL*)(dr + 4);
                const ULL* cp = (const ULL*)(dr + 20);
                ULL ya = 0ull, yb = 0ull;
                #pragma unroll
                for (int k = 0; k < 8; ++k) {
                    ULL tmp = mul2(dtu2, bp[k]);
                    ffma2(tmp, dA2[k], h2[k]);
                    h2[k] = tmp;
                    if (k < 4) ffma2(ya, h2[k], cp[k]);
                    else       ffma2(yb, h2[k], cp[k]);
                }
                float a0v, a1v, b0v, b1v;
                unpack2(ya, a0v, a1v);
                unpack2(yb, b0v, b1v);
                s_uT[tid*TP + t] = ((a0v + b0v) + (a1v + b1v)) + ut*dpv;
            }
        }
        __syncthreads();   // z visible

        // ---- gate z with silu(res) from resh; store tf32-rounded (A of out_proj) ----
        {
            #pragma unroll
            for (int p = 0; p < 21; ++p) {
                ULL z = *((ULL*)&s_uT[tid*TP] + p);
                float z0, z1; unpack2(z, z0, z1);
                float r0 = __half2float(s_resh[tid*TP + 2*p]);
                float r1 = __half2float(s_resh[tid*TP + 2*p + 1]);
                U32 o0 = tf32u(z0 * r0);
                U32 o1 = tf32u(z1 * r1);
                *((ULL*)&s_uT[tid*TP] + p) =
                    pack2f(__uint_as_float(o0), __uint_as_float(o1));
            }
        }

        // ---- out_proj via tf32 mma: [48x128] @ [128x64], += residual ----
        {
            float acc[6][4];
            #pragma unroll
            for (int f = 0; f < 6; ++f)
                #pragma unroll
                for (int j = 0; j < 4; ++j) acc[f][j] = 0.f;
            for (int c = 0; c < 4; ++c) {
                __syncthreads();             // gating done (c=0) / prev chunk compute done
                if (c < 3) {
                    int buf = (c+1) & 1;
                    #pragma unroll
                    for (int k = 0; k < 2; ++k) {
                        int i = k*128 + tid;
                        int row = i >> 4, c16 = i & 15;
                        cp16(swb + (U32)(buf*1152 + row*72 + c16*4)*4u,
                             opw + (c+1)*1024 + row*64 + c16*4);
                    }
                    cp_commit();
                    cp_wait1();
                } else cp_wait0();
                __syncthreads();
                const float* ch_ = s_w + (c & 1)*1152;
                #pragma unroll
                for (int k8 = 0; k8 < 4; ++k8) {
                    U32 b0[2], b1[2];
                    #pragma unroll
                    for (int nt = 0; nt < 2; ++nt) {
                        int col = (2*warp + nt)*8 + g;
                        b0[nt] = *(const U32*)&ch_[(k8*8 + tg)*72 + col];
                        b1[nt] = *(const U32*)&ch_[(k8*8 + tg + 4)*72 + col];
                    }
                    const int kg = c*32 + k8*8;
                    #pragma unroll
                    for (int m = 0; m < 3; ++m) {
                        U32 a0 = *(const U32*)&s_uT[(kg+tg)*TP   + m*16 + g];
                        U32 a1 = *(const U32*)&s_uT[(kg+tg)*TP   + m*16 + g + 8];
                        U32 a2 = *(const U32*)&s_uT[(kg+tg+4)*TP + m*16 + g];
                        U32 a3 = *(const U32*)&s_uT[(kg+tg+4)*TP + m*16 + g + 8];
                        #pragma unroll
                        for (int nt = 0; nt < 2; ++nt)
                            mma_tf32(acc[m*2 + nt], a0, a1, a2, a3, b0[nt], b1[nt]);
                    }
                }
            }
            __syncthreads();
            #pragma unroll
            for (int m = 0; m < 3; ++m)
                #pragma unroll
                for (int nt = 0; nt < 2; ++nt)
                    #pragma unroll
                    for (int j = 0; j < 4; ++j) {
                        int t = m*16 + g + ((j >> 1) & 1)*8;
                        int col = (2*warp + nt)*8 + 2*tg + (j & 1);
                        if (t < LSEQ) s_x[t*DMODEL + col] += acc[m*2 + nt][j];
                    }
        }
    }

    // ---- final rmsnorm + store stack output ----
    __syncthreads();
    {
        float nw0 = norm_f_w[lane], nw1 = norm_f_w[32 + lane];
        for (int t = warp; t < LSEQ; t += 4) {
            float v0 = s_x[t*DMODEL + lane];
            float v1 = s_x[t*DMODEL + 32 + lane];
            float ss = v0*v0 + v1*v1;
            #pragma unroll
            for (int o = 16; o; o >>= 1) ss += __shfl_xor_sync(0xffffffffu, ss, o);
            float inv = rsqrtf(ss * (1.f/64.f) + 1e-5f);
            float* dst = g_stack + ((size_t)(s*BATCH + b)*LSEQ + t)*DMODEL;
            dst[lane]      = v0 * inv * nw0;
            dst[lane + 32] = v1 * inv * nw1;
        }
    }
}

// ---- fuse 3 stacks with softmax(fusion_w) into g_fused ----
__global__ void __launch_bounds__(256)
fuse_stack(const float* __restrict__ fusion_w)
{
    float f0 = fusion_w[0], f1 = fusion_w[1], f2 = fusion_w[2];
    float m = fmaxf(f0, fmaxf(f1, f2));
    float e0 = expf(f0-m), e1 = expf(f1-m), e2 = expf(f2-m);
    float inv = 1.f/(e0+e1+e2);
    e0 *= inv; e1 *= inv; e2 *= inv;
    const size_t SS = (size_t)BATCH * LSEQ * DMODEL;
    size_t i = ((size_t)blockIdx.x*256 + threadIdx.x) * 4;
    if (i < SS) {
        float4 a = *(const float4*)&g_stack[i];
        float4 b = *(const float4*)&g_stack[i + SS];
        float4 c = *(const float4*)&g_stack[i + 2*SS];
        float4 r;
        r.x = e0*a.x + e1*b.x + e2*c.x;
        r.y = e0*a.y + e1*b.y + e2*c.y;
        r.z = e0*a.z + e1*b.z + e2*c.z;
        r.w = e0*a.w + e1*b.w + e2*c.w;
        *(float4*)&g_fused[i] = r;
    }
}

// ---- head GEMM (FFMA2): partial[kz] = g_fused[512x2624] @ W1 chunk; 64x64 tiles, split-K=8 ----
__global__ void __launch_bounds__(256)
head_gemm1(const float* __restrict__ W1)
{
    __shared__ float As[64][33];
    __shared__ float Ws[32][64];
    const int tid = threadIdx.x;
    const int rb = blockIdx.x, cb = blockIdx.y, kz = blockIdx.z;
    const int tx = tid & 15, ty = tid >> 4;
    ULL acc2[4][2];
    #pragma unroll
    for (int r = 0; r < 4; ++r) { acc2[r][0] = 0ull; acc2[r][1] = 0ull; }
    const int KT = LSEQ*DMODEL;   // 2624 = 82 tiles of 32
    const int kt0    = (kz < 2) ? 11*kz : 22 + 10*(kz - 2);
    const int ntiles = (kz < 2) ? 11 : 10;
    for (int it = 0; it < ntiles; ++it) {
        const int kc = kt0 + it;
        __syncthreads();
        #pragma unroll
        for (int i = tid; i < 2048; i += 256) {
            int r = i >> 5, kk = i & 31;
            As[r][kk] = g_fused[(size_t)(rb*64 + r)*KT + kc*32 + kk];
        }
        #pragma unroll
        for (int i = tid; i < 2048; i += 256) {
            int kk = i >> 6, j = i & 63;
            Ws[kk][j] = W1[(size_t)(kc*32 + kk)*384 + cb*64 + j];
        }
        __syncthreads();
        #pragma unroll
        for (int kk = 0; kk < 32; ++kk) {
            const ULL* wp = (const ULL*)&Ws[kk][tx*4];
            ULL w0 = wp[0], w1 = wp[1];
            ULL a0 = pack2(As[ty*4+0][kk]);
            ULL a1 = pack2(As[ty*4+1][kk]);
            ULL a2 = pack2(As[ty*4+2][kk]);
            ULL a3 = pack2(As[ty*4+3][kk]);
            ffma2(acc2[0][0], a0, w0); ffma2(acc2[0][1], a0, w1);
            ffma2(acc2[1][0], a1, w0); ffma2(acc2[1][1], a1, w1);
            ffma2(acc2[2][0], a2, w0); ffma2(acc2[2][1], a2, w1);
            ffma2(acc2[3][0], a3, w0); ffma2(acc2[3][1], a3, w1);
        }
    }
    float* dst = g_h1p + (size_t)kz * BATCH * 384;
    #pragma unroll
    for (int r = 0; r < 4; ++r) {
        int row = rb*64 + ty*4 + r;
        #pragma unroll
        for (int p = 0; p < 2; ++p) {
            float v0, v1; unpack2(acc2[r][p], v0, v1);
            int colg = cb*64 + tx*4 + p*2;
            dst[(size_t)row*384 + colg]     = v0;
            dst[(size_t)row*384 + colg + 1] = v1;
        }
    }
}

// ---- tail: one block per batch row; sum 8 split-K partials ----
__global__ void __launch_bounds__(128)
head_final(const float* __restrict__ b1,
           const float* __restrict__ W2, const float* __restrict__ b2,
           const float* __restrict__ W3, const float* __restrict__ b3,
           float* __restrict__ out)
{
    __shared__ float hv[384];
    __shared__ float part[8][16];
    const int tid = threadIdx.x;
    const int b = blockIdx.x;
    const size_t PS = (size_t)BATCH * 384;
    const float* p0 = g_h1p + (size_t)b*384;
    #pragma unroll
    for (int i = tid; i < 384; i += 128) {
        float v = b1[i];
        #pragma unroll
        for (int k = 0; k < KSPLIT; ++k) v += p0[k*PS + i];
        hv[i] = fmaxf(v, 0.f);
    }
    __syncthreads();
    const int j = tid & 15, seg = tid >> 4;
    float acc = 0.f;
    #pragma unroll 8
    for (int i = seg*48; i < seg*48 + 48; ++i)
        acc += hv[i] * W2[i*16 + j];
    part[seg][j] = acc;
    __syncthreads();
    if (tid < 16) {
        float sum = part[0][tid] + part[1][tid] + part[2][tid] + part[3][tid]
                  + part[4][tid] + part[5][tid] + part[6][tid] + part[7][tid];
        float h2v = fmaxf(sum + b2[tid], 0.f);
        float pr = h2v * W3[tid];
        #pragma unroll
        for (int o = 8; o; o >>= 1) pr += __shfl_xor_sync(0xffffu, pr, o);
        if (tid == 0) out[b] = __fdividef(1.f, 1.f + __expf(-(pr + b3[0])));
    }
}

extern "C" void kernel_launch(void* const* d_in, const int* in_sizes, int n_in,
                              void* d_out, int out_size) {
    const int*   input_ids = (const int*)d_in[0];
    const float* embedding = (const float*)d_in[1];
    const float* in_proj   = (const float*)d_in[2];
    const float* conv_w    = (const float*)d_in[3];
    const float* conv_b    = (const float*)d_in[4];
    const float* x_proj    = (const float*)d_in[5];
    const float* dt_w      = (const float*)d_in[6];
    const float* dt_b      = (const float*)d_in[7];
    const float* A_log     = (const float*)d_in[8];
    const float* Dp        = (const float*)d_in[9];
    const float* out_proj  = (const float*)d_in[10];
    const float* norm_w    = (const float*)d_in[11];
    const float* norm_f_w  = (const float*)d_in[12];
    const float* fusion_w  = (const float*)d_in[13];
    const float* W1        = (const float*)d_in[14];
    const float* b1        = (const float*)d_in[15];
    const float* W2        = (const float*)d_in[16];
    const float* b2        = (const float*)d_in[17];
    const float* W3        = (const float*)d_in[18];
    const float* b3        = (const float*)d_in[19];
    float* out = (float*)d_out;
    (void)in_sizes; (void)n_in; (void)out_size;

    cvt_weights<<<(NSTACK*NLAYER*16384 + 255)/256, 256>>>(in_proj, out_proj, x_proj);

    const int smemA = 18372 * 4;  // 73488 bytes -> 3 CTAs/SM
    cudaFuncSetAttribute(mamba_stack_kernel,
                         cudaFuncAttributeMaxDynamicSharedMemorySize, smemA);
    mamba_stack_kernel<<<dim3(BATCH, NSTACK), 128, smemA>>>(
        input_ids, embedding, conv_w, conv_b, dt_w, dt_b,
        A_log, Dp, norm_w, norm_f_w);
    fuse_stack<<<(BATCH*LSEQ*DMODEL/4 + 255)/256, 256>>>(fusion_w);
    head_gemm1<<<dim3(8, 6, KSPLIT), 256>>>(W1);
    head_final<<<BATCH, 128>>>(b1, W2, b2, W3, b3, out);
}